// round 1
// baseline (speedup 1.0000x reference)
#include <cuda_runtime.h>

// Problem constants (fixed by the dataset): B=1, N=4096, C=8, H=W=128, K=8
#define MAXN 8192
constexpr float RADIUS = 0.05f;
constexpr int H = 128, W = 128, C = 8, K = 8;
constexpr int TILE = 8;           // 8x8 pixel tiles
constexpr int TPB  = TILE * TILE; // 64 threads per block, one per pixel
constexpr int CHUNK = 1024;       // points culled per shared-memory pass

// Scratch for projected points (no cudaMalloc allowed -> __device__ globals)
__device__ float g_px[MAXN];
__device__ float g_py[MAXN];
__device__ float g_z [MAXN];

__global__ void proj_kernel(const float* __restrict__ pts, int n) {
    int i = blockIdx.x * blockDim.x + threadIdx.x;
    if (i < n) {
        float x = pts[3 * i + 0];
        float y = pts[3 * i + 1];
        float z = pts[3 * i + 2];
        g_px[i] = x / z;
        g_py[i] = y / z;
        g_z [i] = z;
    }
}

__global__ void render_kernel(const float* __restrict__ feat,
                              float* __restrict__ out, int n) {
    __shared__ float s_px[CHUNK];
    __shared__ float s_py[CHUNK];
    __shared__ float s_z [CHUNK];
    __shared__ int   s_idx[CHUNK];
    __shared__ int   s_cnt;

    const int tx = blockIdx.x, ty = blockIdx.y;
    const int lx = threadIdx.x & (TILE - 1);
    const int ly = threadIdx.x >> 3;
    const int ix = tx * TILE + lx;
    const int iy = ty * TILE + ly;

    // pixel center in NDC [-1,1]
    const float gx = ((float)ix + 0.5f) / (float)W * 2.0f - 1.0f;
    const float gy = ((float)iy + 0.5f) / (float)H * 2.0f - 1.0f;

    // tile bounds over pixel centers, expanded by splat radius (conservative cull)
    const float x0 = ((float)(tx * TILE)            + 0.5f) / (float)W * 2.0f - 1.0f - RADIUS;
    const float x1 = ((float)(tx * TILE + TILE - 1) + 0.5f) / (float)W * 2.0f - 1.0f + RADIUS;
    const float y0 = ((float)(ty * TILE)            + 0.5f) / (float)H * 2.0f - 1.0f - RADIUS;
    const float y1 = ((float)(ty * TILE + TILE - 1) + 0.5f) / (float)H * 2.0f - 1.0f + RADIUS;

    const float r2 = RADIUS * RADIUS;

    // register-resident top-K, sorted ascending by depth z
    float bz[K], bd[K];
    int   bi[K];
    #pragma unroll
    for (int k = 0; k < K; k++) { bz[k] = 3.0e38f; bd[k] = 0.0f; bi[k] = 0; }

    for (int base = 0; base < n; base += CHUNK) {
        const int cn = min(CHUNK, n - base);
        if (threadIdx.x == 0) s_cnt = 0;
        __syncthreads();

        // cooperative cull: point vs expanded tile rect
        for (int i = threadIdx.x; i < cn; i += TPB) {
            float px = g_px[base + i];
            float py = g_py[base + i];
            float z  = g_z [base + i];
            float dx = fmaxf(fmaxf(x0 - px, px - x1), 0.0f);
            float dy = fmaxf(fmaxf(y0 - py, py - y1), 0.0f);
            if (z > 0.0f && dx * dx + dy * dy < r2) {
                int p = atomicAdd(&s_cnt, 1);
                s_px[p] = px; s_py[p] = py; s_z[p] = z; s_idx[p] = base + i;
            }
        }
        __syncthreads();

        const int cnt = s_cnt;
        for (int j = 0; j < cnt; j++) {
            float dx = gx - s_px[j];
            float dy = gy - s_py[j];
            float d2 = dx * dx + dy * dy;
            float zj = s_z[j];
            // strict '<' on z keeps top_k's stable tie-break (earlier index wins)
            if (d2 < r2 && zj < bz[K - 1]) {
                bz[K - 1] = zj; bd[K - 1] = d2; bi[K - 1] = s_idx[j];
                #pragma unroll
                for (int k = K - 1; k > 0; k--) {
                    if (bz[k] < bz[k - 1]) {
                        float tz = bz[k]; bz[k] = bz[k - 1]; bz[k - 1] = tz;
                        float td = bd[k]; bd[k] = bd[k - 1]; bd[k - 1] = td;
                        int   ti = bi[k]; bi[k] = bi[k - 1]; bi[k - 1] = ti;
                    }
                }
            }
        }
        __syncthreads();
    }

    // front-to-back alpha compositing
    float acc[C];
    #pragma unroll
    for (int c = 0; c < C; c++) acc[c] = 0.0f;
    float T = 1.0f;
    const float inv_r2 = 1.0f / r2;

    #pragma unroll
    for (int k = 0; k < K; k++) {
        if (bz[k] < 1.0e38f) {
            float a = 1.0f - bd[k] * inv_r2;
            a = fminf(fmaxf(a, 0.0f), 1.0f);
            float w = a * T;
            const float4* f = (const float4*)(feat + (size_t)bi[k] * C);
            float4 f0 = f[0];
            float4 f1 = f[1];
            acc[0] += w * f0.x; acc[1] += w * f0.y;
            acc[2] += w * f0.z; acc[3] += w * f0.w;
            acc[4] += w * f1.x; acc[5] += w * f1.y;
            acc[6] += w * f1.z; acc[7] += w * f1.w;
            T *= (1.0f - a);
        }
    }

    float4* o = (float4*)(out + (size_t)(iy * W + ix) * C);
    o[0] = make_float4(acc[0], acc[1], acc[2], acc[3]);
    o[1] = make_float4(acc[4], acc[5], acc[6], acc[7]);
}

extern "C" void kernel_launch(void* const* d_in, const int* in_sizes, int n_in,
                              void* d_out, int out_size) {
    const float* pts  = (const float*)d_in[0];   // [B,N,3] f32
    const float* feat = (const float*)d_in[1];   // [B,N,C] f32
    float* out = (float*)d_out;                  // [B,H,W,C] f32
    int n = in_sizes[0] / 3;                     // B=1 -> N
    if (n > MAXN) n = MAXN;

    proj_kernel<<<(n + 255) / 256, 256>>>(pts, n);

    dim3 grid(W / TILE, H / TILE);
    render_kernel<<<grid, TPB>>>(feat, out, n);
}

// round 2
// speedup vs baseline: 1.6481x; 1.6481x over previous
#include <cuda_runtime.h>

// Problem constants (fixed by dataset): B=1, N=4096, C=8, H=W=128, K=8
#define MAXN 8192
constexpr float RADIUS = 0.05f;
constexpr int H = 128, W = 128, C = 8, K = 8;
constexpr int TILE = 8;             // 8x8 pixel tiles
constexpr int TX = W / TILE;        // 16
constexpr int TY = H / TILE;        // 16
constexpr int NTILES = TX * TY;     // 256
constexpr int TPB = TILE * TILE;    // 64 threads (one per pixel)
constexpr int CAP = 4096;           // per-tile bin capacity (cannot overflow: N<=4096)
constexpr int SCHUNK = 256;         // candidates staged through smem per pass

// Scratch (no cudaMalloc allowed -> __device__ globals)
__device__ int    g_cnt[NTILES];
__device__ float4 g_bins[NTILES * CAP];   // (px, py, z, idx-as-float)

__global__ void zero_kernel() {
    if (threadIdx.x < NTILES) g_cnt[threadIdx.x] = 0;
}

// Project + bin: each point scatters into every tile whose pixel centers it can hit.
// Point radius in pixel units: RADIUS * (W/2) = 3.2 px. Pad to 3.25 for fp safety.
__global__ void bin_kernel(const float* __restrict__ pts, int n) {
    int i = blockIdx.x * blockDim.x + threadIdx.x;
    if (i >= n) return;
    float x = pts[3 * i + 0];
    float y = pts[3 * i + 1];
    float z = pts[3 * i + 2];
    if (z <= 0.0f) return;
    float px = x / z;
    float py = y / z;
    // continuous pixel coordinate of the point: center of pixel ix is at u = ix
    float u = (px + 1.0f) * (0.5f * (float)W) - 0.5f;
    float v = (py + 1.0f) * (0.5f * (float)H) - 0.5f;
    const float PR = 3.25f;  // 3.2 px reach + epsilon
    int tx0 = max(0,      (int)floorf((u - PR) * (1.0f / TILE)));
    int tx1 = min(TX - 1, (int)floorf((u + PR) * (1.0f / TILE)));
    int ty0 = max(0,      (int)floorf((v - PR) * (1.0f / TILE)));
    int ty1 = min(TY - 1, (int)floorf((v + PR) * (1.0f / TILE)));
    if (tx0 > tx1 || ty0 > ty1) return;
    float4 rec = make_float4(px, py, z, __int_as_float(i));
    for (int ty = ty0; ty <= ty1; ty++) {
        for (int tx = tx0; tx <= tx1; tx++) {
            int t = ty * TX + tx;
            int slot = atomicAdd(&g_cnt[t], 1);
            g_bins[t * CAP + slot] = rec;
        }
    }
}

__global__ void render_kernel(const float* __restrict__ feat,
                              float* __restrict__ out) {
    __shared__ float4 sc[SCHUNK];

    const int tx = blockIdx.x, ty = blockIdx.y;
    const int tile = ty * TX + tx;
    const int lx = threadIdx.x & (TILE - 1);
    const int ly = threadIdx.x >> 3;
    const int ix = tx * TILE + lx;
    const int iy = ty * TILE + ly;

    // pixel center in NDC [-1,1]
    const float gx = ((float)ix + 0.5f) * (2.0f / (float)W) - 1.0f;
    const float gy = ((float)iy + 0.5f) * (2.0f / (float)H) - 1.0f;
    const float r2 = RADIUS * RADIUS;

    // register-resident top-K, sorted ascending by depth z
    float bz[K], bd[K];
    int   bi[K];
    #pragma unroll
    for (int k = 0; k < K; k++) { bz[k] = 3.0e38f; bd[k] = 0.0f; bi[k] = 0; }

    const int cnt = g_cnt[tile];
    const float4* __restrict__ bins = &g_bins[tile * CAP];

    for (int base = 0; base < cnt; base += SCHUNK) {
        const int m = min(SCHUNK, cnt - base);
        for (int j = threadIdx.x; j < m; j += TPB)
            sc[j] = bins[base + j];
        __syncthreads();

        for (int j = 0; j < m; j++) {
            float4 c = sc[j];
            float dx = gx - c.x;
            float dy = gy - c.y;
            float d2 = dx * dx + dy * dy;
            // strict '<' on z: distinct depths -> order-independent top-K set
            if (d2 < r2 && c.z < bz[K - 1]) {
                bz[K - 1] = c.z; bd[K - 1] = d2; bi[K - 1] = __float_as_int(c.w);
                #pragma unroll
                for (int k = K - 1; k > 0; k--) {
                    if (bz[k] < bz[k - 1]) {
                        float t0 = bz[k]; bz[k] = bz[k - 1]; bz[k - 1] = t0;
                        float t1 = bd[k]; bd[k] = bd[k - 1]; bd[k - 1] = t1;
                        int   t2 = bi[k]; bi[k] = bi[k - 1]; bi[k - 1] = t2;
                    }
                }
            }
        }
        __syncthreads();
    }

    // front-to-back alpha compositing
    float acc[C];
    #pragma unroll
    for (int c = 0; c < C; c++) acc[c] = 0.0f;
    float T = 1.0f;
    const float inv_r2 = 1.0f / r2;

    #pragma unroll
    for (int k = 0; k < K; k++) {
        if (bz[k] < 1.0e38f) {
            float a = 1.0f - bd[k] * inv_r2;
            a = fminf(fmaxf(a, 0.0f), 1.0f);
            float w = a * T;
            const float4* f = (const float4*)(feat + (size_t)bi[k] * C);
            float4 f0 = __ldg(&f[0]);
            float4 f1 = __ldg(&f[1]);
            acc[0] += w * f0.x; acc[1] += w * f0.y;
            acc[2] += w * f0.z; acc[3] += w * f0.w;
            acc[4] += w * f1.x; acc[5] += w * f1.y;
            acc[6] += w * f1.z; acc[7] += w * f1.w;
            T *= (1.0f - a);
        }
    }

    float4* o = (float4*)(out + (size_t)(iy * W + ix) * C);
    o[0] = make_float4(acc[0], acc[1], acc[2], acc[3]);
    o[1] = make_float4(acc[4], acc[5], acc[6], acc[7]);
}

extern "C" void kernel_launch(void* const* d_in, const int* in_sizes, int n_in,
                              void* d_out, int out_size) {
    const float* pts  = (const float*)d_in[0];   // [B,N,3] f32
    const float* feat = (const float*)d_in[1];   // [B,N,C] f32
    float* out = (float*)d_out;                  // [B,H,W,C] f32
    int n = in_sizes[0] / 3;                     // B=1 -> N
    if (n > MAXN) n = MAXN;

    zero_kernel<<<1, 256>>>();
    bin_kernel<<<(n + 255) / 256, 256>>>(pts, n);
    dim3 grid(TX, TY);
    render_kernel<<<grid, TPB>>>(feat, out);
}